// round 3
// baseline (speedup 1.0000x reference)
#include <cuda_runtime.h>
#include <math_constants.h>
#include <stdint.h>

#define N_ATOM   6144
#define NTOT     18432
#define TPB      384
#define TILE     384
#define TSTRIPS  16
#define NTILES   136                 /* 16*17/2 */
#define NQBLK    2
#define GRID     (NQBLK + 1 + NTILES)/* 139 */
#define EPT      (NTOT / TPB)        /* 48 */
#define GMAX     2048
#define SMEM_BYTES 8192              /* gather buf 2048 f32; pairwise 3*TILE f32 = 4608B */
#define NWARPS   (TPB / 32)

static const double NPAIRS_D = 18871296.0;  /* 6144*6143/2 */
static const double RAND_STD = 1.75;
static const double IQR_RAND = 2.45;

__device__ double   g_pair_partial[NTILES];
__device__ double   g_sum_d, g_sumsq_d;
__device__ float    g_qv[4];
__device__ unsigned g_done = 0;

/* ---------------- helpers ---------------- */
__device__ __forceinline__ float sqrt_approx(float x) {
    float r; asm("sqrt.approx.f32 %0, %1;" : "=f"(r) : "f"(x)); return r;
}
typedef unsigned long long u64;
__device__ __forceinline__ u64 addx2(u64 a, u64 b) {
    u64 r; asm("add.rn.f32x2 %0, %1, %2;" : "=l"(r) : "l"(a), "l"(b)); return r;
}
__device__ __forceinline__ u64 mulx2(u64 a, u64 b) {
    u64 r; asm("mul.rn.f32x2 %0, %1, %2;" : "=l"(r) : "l"(a), "l"(b)); return r;
}
__device__ __forceinline__ u64 fmax2(u64 a, u64 b, u64 c) {
    u64 r; asm("fma.rn.f32x2 %0, %1, %2, %3;" : "=l"(r) : "l"(a), "l"(b), "l"(c)); return r;
}
__device__ __forceinline__ u64 pack2(float lo, float hi) {
    u64 r; asm("mov.b64 %0, {%1, %2};" : "=l"(r) : "f"(lo), "f"(hi)); return r;
}
__device__ __forceinline__ void unpack2(u64 v, float& lo, float& hi) {
    asm("mov.b64 {%0, %1}, %2;" : "=f"(lo), "=f"(hi) : "l"(v));
}
/* monotone float->uint key (order preserving, handles +-inf) */
__device__ __forceinline__ unsigned fkey(float f) {
    unsigned u = __float_as_uint(f);
    return (u & 0x80000000u) ? ~u : (u | 0x80000000u);
}
__device__ __forceinline__ float funkey(unsigned u) {
    unsigned bits = (u & 0x80000000u) ? (u & 0x7fffffffu) : ~u;
    return __uint_as_float(bits);
}

__global__ void __launch_bounds__(TPB)
dp_fused_kernel(const float* __restrict__ g, float* __restrict__ out) {
    extern __shared__ unsigned char smem_raw[];
    const int bid = blockIdx.x;
    const int t   = threadIdx.x;
    const int w   = t >> 5;
    const int ln  = t & 31;

    __shared__ unsigned s_wcnt[NWARPS];
    __shared__ unsigned s_tot, s_gcnt;
    __shared__ float    s_fred[NWARPS];
    __shared__ int      s_last;

    if (bid < NQBLK) {
        /* ============ exact quantile pair (ranks k0, k0+1) ============ */
        const int qb = bid;
        const unsigned k0 = qb ? 13823u : 4607u;  /* q3 : q1 */
        const float gA = qb ? 0.6245f : -0.7245f; /* +-0.6745 -+ 0.05 */
        const float gB = qb ? 0.7245f : -0.6245f;

        float v[EPT];
        #pragma unroll
        for (int e = 0; e < EPT; ++e) v[e] = g[t + e * TPB];

        float lo = -CUDART_INF_F, hi = CUDART_INF_F;
        unsigned cL = 0, cH = NTOT;
        bool allEq = false;

        for (int it = 0; it < 48; ++it) {
            if (cH - cL <= (unsigned)GMAX) break;
            const unsigned klo = fkey(lo), khi = fkey(hi);
            if (khi - klo <= 1u) { allEq = true; break; }
            float cand;
            if (it == 0)      cand = gA;
            else if (it == 1) cand = gB;
            else if (it < 8) {
                double frac = ((double)k0 + 0.5 - (double)cL) / (double)(cH - cL);
                cand = (float)((double)lo + frac * ((double)hi - (double)lo));
            } else cand = funkey(klo + (khi - klo) / 2u);
            {   /* validate cand strictly inside (lo,hi); else key-midpoint */
                unsigned kc = fkey(cand);
                if (!(kc > klo && kc < khi)) cand = funkey(klo + (khi - klo) / 2u);
            }
            unsigned c = 0;
            #pragma unroll
            for (int e = 0; e < EPT; ++e) c += (v[e] < cand) ? 1u : 0u;
            #pragma unroll
            for (int o = 16; o; o >>= 1) c += __shfl_down_sync(0xffffffffu, c, o);
            if (ln == 0) s_wcnt[w] = c;
            __syncthreads();
            if (t == 0) {
                unsigned tot = 0;
                #pragma unroll
                for (int i = 0; i < NWARPS; ++i) tot += s_wcnt[i];
                s_tot = tot;
            }
            __syncthreads();
            const unsigned ctot = s_tot;
            if (ctot <= k0) { lo = cand; cL = ctot; }
            else            { hi = cand; cH = ctot; }
        }

        const unsigned m  = cH - cL;
        const unsigned r0 = k0 - cL;
        const unsigned r1 = r0 + 1u;

        if (allEq) {
            if (t == 0) g_qv[2 * qb + 0] = lo;
            if (r1 < m) { if (t == 0) g_qv[2 * qb + 1] = lo; }
        } else {
            /* gather [lo, hi) into smem, exact select ranks r0, r1 */
            float* sub = (float*)smem_raw;
            if (t == 0) s_gcnt = 0;
            __syncthreads();
            #pragma unroll
            for (int e = 0; e < EPT; ++e) {
                float x = v[e];
                if (x >= lo && x < hi) {
                    unsigned p = atomicAdd(&s_gcnt, 1u);
                    if (p < (unsigned)GMAX) sub[p] = x;
                }
            }
            __syncthreads();
            const unsigned mm = s_gcnt;  /* == m */
            for (unsigned i = t; i < mm; i += TPB) {
                float x = sub[i];
                unsigned cl = 0, ce = 0;
                for (unsigned jj = 0; jj < mm; ++jj) {
                    float y = sub[jj];
                    cl += (y < x) ? 1u : 0u;
                    ce += (y == x) ? 1u : 0u;
                }
                if (cl <= r0 && r0 < cl + ce) g_qv[2 * qb + 0] = x;
                if (r1 < mm && cl <= r1 && r1 < cl + ce) g_qv[2 * qb + 1] = x;
            }
        }
        if (r1 >= m) {
            /* v[k0+1] == min element >= hi (hi finite here) */
            float mn = CUDART_INF_F;
            #pragma unroll
            for (int e = 0; e < EPT; ++e)
                if (v[e] >= hi) mn = fminf(mn, v[e]);
            #pragma unroll
            for (int o = 16; o; o >>= 1)
                mn = fminf(mn, __shfl_down_sync(0xffffffffu, mn, o));
            if (ln == 0) s_fred[w] = mn;
            __syncthreads();
            if (t == 0) {
                float r = s_fred[0];
                #pragma unroll
                for (int i = 1; i < NWARPS; ++i) r = fminf(r, s_fred[i]);
                g_qv[2 * qb + 1] = r;
            }
        }

    } else if (bid == NQBLK) {
        /* ============ std sums (fp64, deterministic) ============ */
        __shared__ double sds[NWARPS], sdq[NWARPS];
        double s = 0.0, s2 = 0.0;
        #pragma unroll
        for (int e = 0; e < EPT; ++e) {
            double x = (double)g[t + e * TPB];
            s += x; s2 += x * x;
        }
        #pragma unroll
        for (int o = 16; o; o >>= 1) {
            s  += __shfl_down_sync(0xffffffffu, s,  o);
            s2 += __shfl_down_sync(0xffffffffu, s2, o);
        }
        if (ln == 0) { sds[w] = s; sdq[w] = s2; }
        __syncthreads();
        if (t == 0) {
            double a = 0.0, b = 0.0;
            #pragma unroll
            for (int i = 0; i < NWARPS; ++i) { a += sds[i]; b += sdq[i]; }
            g_sum_d = a; g_sumsq_d = b;
        }

    } else {
        /* ============ pairwise: tile (a,b), a<=b; accumulate sqrt(min(sq,0.64)) ==== */
        const int idx = bid - (NQBLK + 1);
        int a = 0, rem = idx;
        while (rem >= TSTRIPS - a) { rem -= TSTRIPS - a; ++a; }
        const int b = a + rem;

        float* snx = (float*)smem_raw;      /* negated j coords */
        float* sny = snx + TILE;
        float* snz = sny + TILE;

        const int j = b * TILE + t;
        snx[t] = -g[3 * j + 0];
        sny[t] = -g[3 * j + 1];
        snz[t] = -g[3 * j + 2];
        __syncthreads();

        const int i = a * TILE + t;
        const float xi = g[3 * i + 0];
        const float yi = g[3 * i + 1];
        const float zi = g[3 * i + 2];

        float a0 = 0.f, a1 = 0.f, a2 = 0.f, a3 = 0.f;

        if (a == b) {
            for (int jj = t + 1; jj < TILE; ++jj) {
                float dx = xi + snx[jj], dy = yi + sny[jj], dz = zi + snz[jj];
                float sq = fmaf(dz, dz, fmaf(dy, dy, dx * dx));
                a0 += sqrt_approx(fminf(sq, 0.64f));
            }
        } else {
            const u64 xi2 = pack2(xi, xi);
            const u64 yi2 = pack2(yi, yi);
            const u64 zi2 = pack2(zi, zi);
            const u64* px = (const u64*)snx;
            const u64* py = (const u64*)sny;
            const u64* pz = (const u64*)snz;
            #pragma unroll 2
            for (int m = 0; m < TILE / 2; m += 2) {
                {
                    u64 dx = addx2(xi2, px[m]);
                    u64 dy = addx2(yi2, py[m]);
                    u64 dz = addx2(zi2, pz[m]);
                    u64 sq = mulx2(dx, dx);
                    sq = fmax2(dy, dy, sq);
                    sq = fmax2(dz, dz, sq);
                    float s0, s1; unpack2(sq, s0, s1);
                    a0 += sqrt_approx(fminf(s0, 0.64f));
                    a1 += sqrt_approx(fminf(s1, 0.64f));
                }
                {
                    u64 dx = addx2(xi2, px[m + 1]);
                    u64 dy = addx2(yi2, py[m + 1]);
                    u64 dz = addx2(zi2, pz[m + 1]);
                    u64 sq = mulx2(dx, dx);
                    sq = fmax2(dy, dy, sq);
                    sq = fmax2(dz, dz, sq);
                    float s0, s1; unpack2(sq, s0, s1);
                    a2 += sqrt_approx(fminf(s0, 0.64f));
                    a3 += sqrt_approx(fminf(s1, 0.64f));
                }
            }
        }

        /* block reduction: warp shfl + cross-warp (correct for TPB=384) */
        float tot = (a0 + a1) + (a2 + a3);
        #pragma unroll
        for (int o = 16; o; o >>= 1)
            tot += __shfl_down_sync(0xffffffffu, tot, o);
        if (ln == 0) s_fred[w] = tot;
        __syncthreads();
        if (t == 0) {
            float r = 0.f;
            #pragma unroll
            for (int i2 = 0; i2 < NWARPS; ++i2) r += s_fred[i2];
            g_pair_partial[idx] = (double)r;
        }
    }

    /* ============ fused combine: last block finishing does the epilogue ====== */
    __threadfence();
    __syncthreads();
    if (t == 0) {
        unsigned old = atomicAdd(&g_done, 1u);
        s_last = (old == (unsigned)(GRID - 1)) ? 1 : 0;
    }
    __syncthreads();
    if (s_last) {
        __threadfence();
        if (t < 32) {
            double s = 0.0;
            for (int i2 = t; i2 < NTILES; i2 += 32) s += g_pair_partial[i2];
            #pragma unroll
            for (int o = 16; o; o >>= 1) s += __shfl_down_sync(0xffffffffu, s, o);
            if (t == 0) {
                double punish = 0.8 - s / NPAIRS_D;
                double var = (g_sumsq_d - g_sum_d * g_sum_d / (double)NTOT)
                             / (double)(NTOT - 1);
                double sd = sqrt(var);
                float q1 = 0.25f * g_qv[0] + 0.75f * g_qv[1];
                float q3 = 0.75f * g_qv[2] + 0.25f * g_qv[3];
                double dstd = sd - RAND_STD;
                double diqr = (double)(q3 - q1) - IQR_RAND;
                out[0] = (float)(punish + dstd * dstd + diqr * diqr);
                g_done = 0;  /* reset for next graph replay */
            }
        }
    }
}

extern "C" void kernel_launch(void* const* d_in, const int* in_sizes, int n_in,
                              void* d_out, int out_size) {
    (void)in_sizes; (void)n_in; (void)out_size;
    const float* g = (const float*)d_in[0];
    float* out = (float*)d_out;
    dp_fused_kernel<<<GRID, TPB, SMEM_BYTES>>>(g, out);
}